// round 8
// baseline (speedup 1.0000x reference)
#include <cuda_runtime.h>
#include <cuda_bf16.h>
#include <cstdint>

// out[b*64+n][o] = (1/16) * sum_f x[b*64+n][f] * W[n][f][o]
// 64 GEMMs: A_n [4096 x 256] (row stride 16384 floats) @ B_n [256 x 256].
// bf16 3-term split HMMA. 128-thread CTAs (4 warps @ 64x64), 128x128 CTA tile,
// 3-stage cp.async pipeline, 2 CTAs/SM.

#define NUM_NODES 64
#define BATCH     4096
#define RS        16384

#define BM 128
#define BN 128
#define NCHUNK 8
#define THREADS 128

// stage layout (bytes): Ahi 8K | Alo 8K | Bhi 8K | Blo 8K = 32K per stage
#define STG  32768
#define OAH  0
#define OAL  8192
#define OBH  16384
#define OBL  24576
#define SMEM_TOTAL (3 * STG)   // 98304 per CTA -> 2 CTAs/SM

// W pre-split + pre-swizzled: g_W*[ (node*8 + chunk)*16384 + swz(n*64 + kl*2) ]
__device__ __align__(16) unsigned char g_Whi[NUM_NODES * 8 * 16384];
__device__ __align__(16) unsigned char g_Wlo[NUM_NODES * 8 * 16384];

// ======================= helpers =======================
__device__ __forceinline__ uint32_t swz(uint32_t x) { return x ^ ((x >> 3) & 0x70); }
__device__ __forceinline__ uint32_t smem_u32(const void* p) {
    uint32_t a;
    asm("{ .reg .u64 t; cvta.to.shared.u64 t, %1; cvt.u32.u64 %0, t; }" : "=r"(a) : "l"(p));
    return a;
}
__device__ __forceinline__ void cp16(uint32_t d, const void* s) {
    asm volatile("cp.async.cg.shared.global [%0], [%1], 16;" :: "r"(d), "l"(s) : "memory");
}
__device__ __forceinline__ void ldmx4(uint32_t* r, uint32_t a) {
    asm volatile("ldmatrix.sync.aligned.m8n8.x4.shared.b16 {%0,%1,%2,%3}, [%4];"
                 : "=r"(r[0]), "=r"(r[1]), "=r"(r[2]), "=r"(r[3]) : "r"(a));
}
__device__ __forceinline__ void mma16816(float* c, const uint32_t* a, uint32_t b0, uint32_t b1) {
    asm volatile(
        "mma.sync.aligned.m16n8k16.row.col.f32.bf16.bf16.f32 "
        "{%0,%1,%2,%3}, {%4,%5,%6,%7}, {%8,%9}, {%0,%1,%2,%3};"
        : "+f"(c[0]), "+f"(c[1]), "+f"(c[2]), "+f"(c[3])
        : "r"(a[0]), "r"(a[1]), "r"(a[2]), "r"(a[3]), "r"(b0), "r"(b1));
}
__device__ __forceinline__ uint32_t packbf2(__nv_bfloat16 a, __nv_bfloat16 b) {
    return (uint32_t)__bfloat16_as_ushort(a) | ((uint32_t)__bfloat16_as_ushort(b) << 16);
}
__device__ __forceinline__ void split1(float v, __nv_bfloat16& h, __nv_bfloat16& l) {
    h = __float2bfloat16(v);
    l = __float2bfloat16(v - __bfloat162float(h));
}
__device__ __forceinline__ void sts16(uint32_t addr, uint32_t a, uint32_t b, uint32_t c, uint32_t d) {
    asm volatile("st.shared.v4.b32 [%0], {%1,%2,%3,%4};"
                 :: "r"(addr), "r"(a), "r"(b), "r"(c), "r"(d) : "memory");
}

// ======================= prep: W -> split bf16, swizzled tiles =======================
__global__ __launch_bounds__(256)
void prep_w(const float* __restrict__ W) {
    __shared__ __align__(16) unsigned char shi[16384];
    __shared__ __align__(16) unsigned char slo[16384];
    const int node = blockIdx.x >> 3;
    const int c    = blockIdx.x & 7;
    const int o    = threadIdx.x;

    const float* src = W + (size_t)node * 65536 + (size_t)c * 32 * 256 + o;
    #pragma unroll 4
    for (int fl = 0; fl < 32; fl++) {
        float v = src[(size_t)fl * 256];
        __nv_bfloat16 h, l;
        split1(v, h, l);
        const uint32_t ad = swz((uint32_t)(o * 64 + fl * 2));
        *reinterpret_cast<__nv_bfloat16*>(shi + ad) = h;
        *reinterpret_cast<__nv_bfloat16*>(slo + ad) = l;
    }
    __syncthreads();

    const size_t off = (size_t)blockIdx.x * 16384;
    const float4* ph = reinterpret_cast<const float4*>(shi);
    const float4* pl = reinterpret_cast<const float4*>(slo);
    float4* dh = reinterpret_cast<float4*>(g_Whi + off);
    float4* dl = reinterpret_cast<float4*>(g_Wlo + off);
    #pragma unroll
    for (int i = 0; i < 4; i++) {
        const int idx = threadIdx.x + i * 256;
        dh[idx] = ph[idx];
        dl[idx] = pl[idx];
    }
}

// ======================= main GEMM =======================
__global__ __launch_bounds__(THREADS, 2)
void node_gemm_hmma(const float* __restrict__ x, float* __restrict__ out) {
    extern __shared__ unsigned char sm[];
    const uint32_t smb = smem_u32(sm);
    const int t    = threadIdx.x;
    const int lane = t & 31;
    const int wid  = t >> 5;        // 0..3
    const int wm   = wid >> 1;      // 0..1 -> m offset wm*64
    const int wn   = wid & 1;       // 0..1 -> n offset wn*64
    const int node = blockIdx.z;
    const int m0   = blockIdx.x * BM;
    const int n0   = blockIdx.y * BN;

    // ---- A global-load role: thread t owns row t, 32 floats per chunk ----
    const float* ag = x + (size_t)node * 256 + (size_t)(m0 + t) * RS;
    uint32_t asts[4];
    #pragma unroll
    for (int i = 0; i < 4; i++)
        asts[i] = swz((uint32_t)(t * 64 + i * 16));

    // ---- fragment ldmatrix LINEAR base offsets; swz applied per k-half use.
    //      +1024-per-16-rows jumps are swizzle-invariant. ----
    const int aq = lane >> 3;
    const uint32_t aoff_lin = (uint32_t)((wm * 64 + (aq & 1) * 8 + (lane & 7)) * 64 +
                                         (aq >> 1) * 16);
    const uint32_t boff_lin = (uint32_t)((wn * 64 + ((lane >> 4) & 1) * 8 + (lane & 7)) * 64 +
                                         ((lane >> 3) & 1) * 16);

    float acc[4][8][4];
    #pragma unroll
    for (int mi = 0; mi < 4; mi++)
        #pragma unroll
        for (int nf = 0; nf < 8; nf++)
            #pragma unroll
            for (int r = 0; r < 4; r++) acc[mi][nf][r] = 0.f;

    auto cpB = [&](int c, int s) {
        // n-rows [n0, n0+128): swizzle uses addr bits[7:9] only, so the 8KB
        // sub-block at byte offset n0*64 keeps a self-consistent local swizzle.
        const unsigned char* gh = g_Whi + (size_t)(node * 8 + c) * 16384 + n0 * 64;
        const unsigned char* gl = g_Wlo + (size_t)(node * 8 + c) * 16384 + n0 * 64;
        const uint32_t sb = smb + s * STG;
        #pragma unroll
        for (int j = 0; j < 4; j++) {
            const uint32_t o = (uint32_t)(t + j * 128) * 16;
            cp16(sb + OBH + o, gh + o);
            cp16(sb + OBL + o, gl + o);
        }
        asm volatile("cp.async.commit_group;" ::: "memory");
    };
    auto ldA = [&](int c, float4* v) {
        #pragma unroll
        for (int j = 0; j < 8; j++)
            v[j] = *reinterpret_cast<const float4*>(ag + c * 32 + j * 4);
    };
    auto stsA = [&](int s, const float4* v) {
        const uint32_t sb = smb + s * STG;
        #pragma unroll
        for (int i = 0; i < 4; i++) {   // 8 floats -> 16B hi + 16B lo
            __nv_bfloat16 h0,l0,h1,l1,h2,l2,h3,l3,h4,l4,h5,l5,h6,l6,h7,l7;
            split1(v[2*i].x, h0, l0);   split1(v[2*i].y, h1, l1);
            split1(v[2*i].z, h2, l2);   split1(v[2*i].w, h3, l3);
            split1(v[2*i+1].x, h4, l4); split1(v[2*i+1].y, h5, l5);
            split1(v[2*i+1].z, h6, l6); split1(v[2*i+1].w, h7, l7);
            sts16(sb + OAH + asts[i], packbf2(h0,h1), packbf2(h2,h3),
                                      packbf2(h4,h5), packbf2(h6,h7));
            sts16(sb + OAL + asts[i], packbf2(l0,l1), packbf2(l2,l3),
                                      packbf2(l4,l5), packbf2(l6,l7));
        }
    };

    // ---- prologue: chunks 0,1 ----
    cpB(0, 0);
    {
        float4 a0[8];
        ldA(0, a0);
        stsA(0, a0);
    }
    cpB(1, 1);
    {
        float4 a1[8];
        ldA(1, a1);
        stsA(1, a1);
    }
    asm volatile("cp.async.wait_group 1;" ::: "memory");
    __syncthreads();

    // ---- mainloop: one barrier per chunk ----
    for (int c = 0; c < NCHUNK; c++) {
        const int s = c % 3;
        const uint32_t sb = smb + s * STG;

        float4 av[8];
        if (c + 2 < NCHUNK) {
            ldA(c + 2, av);               // LDG latency hidden under MMAs below
            cpB(c + 2, (c + 2) % 3);
        }

        #pragma unroll
        for (int h = 0; h < 2; h++) {
            const uint32_t aswz = swz(aoff_lin + h * 32);
            const uint32_t bswz = swz(boff_lin + h * 32);
            uint32_t Ah[4][4], Al[4][4], B[4][4];
            #pragma unroll
            for (int mi = 0; mi < 4; mi++) ldmx4(Ah[mi], sb + OAH + aswz + mi * 1024);
            #pragma unroll
            for (int mi = 0; mi < 4; mi++) ldmx4(Al[mi], sb + OAL + aswz + mi * 1024);
            #pragma unroll
            for (int g = 0; g < 4; g++) ldmx4(B[g], sb + OBH + bswz + g * 1024);

            #pragma unroll
            for (int g = 0; g < 4; g++)
                #pragma unroll
                for (int gg = 0; gg < 2; gg++) {
                    const int nf = 2 * g + gg;
                    #pragma unroll
                    for (int mi = 0; mi < 4; mi++)
                        mma16816(acc[mi][nf], Ah[mi], B[g][gg * 2], B[g][gg * 2 + 1]);
                    #pragma unroll
                    for (int mi = 0; mi < 4; mi++)
                        mma16816(acc[mi][nf], Al[mi], B[g][gg * 2], B[g][gg * 2 + 1]);
                }

            #pragma unroll
            for (int g = 0; g < 4; g++) ldmx4(B[g], sb + OBL + bswz + g * 1024);
            #pragma unroll
            for (int g = 0; g < 4; g++)
                #pragma unroll
                for (int gg = 0; gg < 2; gg++) {
                    const int nf = 2 * g + gg;
                    #pragma unroll
                    for (int mi = 0; mi < 4; mi++)
                        mma16816(acc[mi][nf], Ah[mi], B[g][gg * 2], B[g][gg * 2 + 1]);
                }
        }

        if (c + 2 < NCHUNK) stsA((c + 2) % 3, av);
        if (c < NCHUNK - 1) {
            if (c < NCHUNK - 2) {
                asm volatile("cp.async.wait_group 1;" ::: "memory");
            } else {
                asm volatile("cp.async.wait_group 0;" ::: "memory");
            }
            __syncthreads();
        }
    }

    // ---- epilogue: registers -> gmem, scale 1/16 ----
    const float sc = 0.0625f;
    float* ob = out + (size_t)node * 256 + n0;
    const int ecol0 = wn * 64 + (lane & 3) * 2;
    #pragma unroll
    for (int mi = 0; mi < 4; mi++) {
        const int erow = m0 + wm * 64 + mi * 16 + (lane >> 2);
        #pragma unroll
        for (int nf = 0; nf < 8; nf++) {
            float* p0 = ob + (size_t)erow * RS + ecol0 + nf * 8;
            float* p1 = p0 + (size_t)8 * RS;
            float2 v0, v1;
            v0.x = acc[mi][nf][0] * sc; v0.y = acc[mi][nf][1] * sc;
            v1.x = acc[mi][nf][2] * sc; v1.y = acc[mi][nf][3] * sc;
            *reinterpret_cast<float2*>(p0) = v0;
            *reinterpret_cast<float2*>(p1) = v1;
        }
    }
}

// ======================= launch =======================
extern "C" void kernel_launch(void* const* d_in, const int* in_sizes, int n_in,
                              void* d_out, int out_size)
{
    const float* x = (const float*)d_in[0];   // [262144, 256] f32
    const float* W = (const float*)d_in[2];   // [64, 256, 256] f32
    float*     out = (float*)d_out;

    cudaFuncSetAttribute(node_gemm_hmma, cudaFuncAttributeMaxDynamicSharedMemorySize, SMEM_TOTAL);

    prep_w<<<NUM_NODES * 8, 256>>>(W);
    node_gemm_hmma<<<dim3(BATCH / BM, 256 / BN, NUM_NODES), THREADS, SMEM_TOTAL>>>(x, out);
}

// round 9
// speedup vs baseline: 1.8485x; 1.8485x over previous
#include <cuda_runtime.h>
#include <cuda_fp16.h>
#include <cstdint>

// out[b*64+n][o] = (1/16) * sum_f x[b*64+n][f] * W[n][f][o]
// 64 GEMMs: A_n [4096 x 256] (row stride 16384 floats) @ B_n [256 x 256].
// Single-pass fp16 HMMA (fp32 accum). 256 threads, 8 warps @ 64x64 warp tile,
// BM=128 x BN=256 CTA tile, 4-stage cp.async pipeline.

#define NUM_NODES 64
#define BATCH     4096
#define RS        16384

#define BM 128
#define NCHUNK 8
#define THREADS 256

// stage layout (bytes): A 8K ([128 rows x 32 k] fp16, 64B rows, SW128)
//                       B 16K ([256 rows x 32 k] fp16, 64B rows, SW128)
#define STG  24576
#define OA   0
#define OB   8192
#define NSTAGE 4
#define SMEM_TOTAL (NSTAGE * STG)   // 98304

// W pre-converted fp16, pre-swizzled: g_Wh[(node*8+chunk)*16384 + swz(n*64 + kl*2)]
__device__ __align__(16) unsigned char g_Wh[NUM_NODES * 8 * 16384];

// ======================= helpers =======================
__device__ __forceinline__ uint32_t swz(uint32_t x) { return x ^ ((x >> 3) & 0x70); }
__device__ __forceinline__ uint32_t smem_u32(const void* p) {
    uint32_t a;
    asm("{ .reg .u64 t; cvta.to.shared.u64 t, %1; cvt.u32.u64 %0, t; }" : "=r"(a) : "l"(p));
    return a;
}
__device__ __forceinline__ void cp16(uint32_t d, const void* s) {
    asm volatile("cp.async.cg.shared.global [%0], [%1], 16;" :: "r"(d), "l"(s) : "memory");
}
__device__ __forceinline__ void ldmx4(uint32_t* r, uint32_t a) {
    asm volatile("ldmatrix.sync.aligned.m8n8.x4.shared.b16 {%0,%1,%2,%3}, [%4];"
                 : "=r"(r[0]), "=r"(r[1]), "=r"(r[2]), "=r"(r[3]) : "r"(a));
}
__device__ __forceinline__ void mma16816(float* c, const uint32_t* a, uint32_t b0, uint32_t b1) {
    asm volatile(
        "mma.sync.aligned.m16n8k16.row.col.f32.f16.f16.f32 "
        "{%0,%1,%2,%3}, {%4,%5,%6,%7}, {%8,%9}, {%0,%1,%2,%3};"
        : "+f"(c[0]), "+f"(c[1]), "+f"(c[2]), "+f"(c[3])
        : "r"(a[0]), "r"(a[1]), "r"(a[2]), "r"(a[3]), "r"(b0), "r"(b1));
}
__device__ __forceinline__ uint32_t packh2(float a, float b) {
    __half2 h = __floats2half2_rn(a, b);
    return *reinterpret_cast<uint32_t*>(&h);
}
__device__ __forceinline__ void sts16(uint32_t addr, uint32_t a, uint32_t b, uint32_t c, uint32_t d) {
    asm volatile("st.shared.v4.b32 [%0], {%1,%2,%3,%4};"
                 :: "r"(addr), "r"(a), "r"(b), "r"(c), "r"(d) : "memory");
}

// ======================= prep: W -> fp16, swizzled tiles =======================
__global__ __launch_bounds__(256)
void prep_w(const float* __restrict__ W) {
    __shared__ __align__(16) unsigned char sh[16384];
    const int node = blockIdx.x >> 3;
    const int c    = blockIdx.x & 7;
    const int o    = threadIdx.x;            // n index, coalesced across lanes

    const float* src = W + (size_t)node * 65536 + (size_t)c * 32 * 256 + o;
    #pragma unroll 4
    for (int fl = 0; fl < 32; fl++) {
        float v = src[(size_t)fl * 256];
        const uint32_t ad = swz((uint32_t)(o * 64 + fl * 2));
        *reinterpret_cast<__half*>(sh + ad) = __float2half_rn(v);
    }
    __syncthreads();

    const size_t off = (size_t)blockIdx.x * 16384;
    const float4* ph = reinterpret_cast<const float4*>(sh);
    float4* dh = reinterpret_cast<float4*>(g_Wh + off);
    #pragma unroll
    for (int i = 0; i < 4; i++) {
        const int idx = threadIdx.x + i * 256;
        dh[idx] = ph[idx];
    }
}

// ======================= main GEMM =======================
__global__ __launch_bounds__(THREADS, 1)
void node_gemm_hmma(const float* __restrict__ x, float* __restrict__ out) {
    extern __shared__ unsigned char sm[];
    const uint32_t smb = smem_u32(sm);
    const int t    = threadIdx.x;
    const int lane = t & 31;
    const int wid  = t >> 5;
    const int wm   = wid >> 2;      // 0..1 -> m offset wm*64
    const int wn   = wid & 3;       // 0..3 -> n offset wn*64
    const int node = blockIdx.y;
    const int m0   = blockIdx.x * BM;

    // ---- A global-load role: thread t owns row t>>1, 16 of 32 floats per chunk ----
    const int arow = t >> 1;
    const int ah16 = (t & 1) * 16;
    const float* ag = x + (size_t)node * 256 + (size_t)(m0 + arow) * RS + ah16;
    uint32_t asts[2];
    #pragma unroll
    for (int i = 0; i < 2; i++)
        asts[i] = swz((uint32_t)(arow * 64 + ah16 * 2 + i * 16));

    // ---- fragment ldmatrix LINEAR base offsets; swz applied per k-half use ----
    const int aq = lane >> 3;
    const uint32_t aoff_lin = (uint32_t)((wm * 64 + (aq & 1) * 8 + (lane & 7)) * 64 +
                                         (aq >> 1) * 16);
    const uint32_t boff_lin = (uint32_t)((wn * 64 + ((lane >> 4) & 1) * 8 + (lane & 7)) * 64 +
                                         ((lane >> 3) & 1) * 16);

    float acc[4][8][4];
    #pragma unroll
    for (int mi = 0; mi < 4; mi++)
        #pragma unroll
        for (int nf = 0; nf < 8; nf++)
            #pragma unroll
            for (int r = 0; r < 4; r++) acc[mi][nf][r] = 0.f;

    auto cpB = [&](int c, int s) {
        const unsigned char* gh = g_Wh + (size_t)(node * 8 + c) * 16384;
        const uint32_t sb = smb + s * STG + OB;
        #pragma unroll
        for (int j = 0; j < 4; j++) {
            const uint32_t o = (uint32_t)(t + j * 256) * 16;
            cp16(sb + o, gh + o);
        }
        asm volatile("cp.async.commit_group;" ::: "memory");
    };
    auto ldA = [&](int c, float4* v) {
        #pragma unroll
        for (int j = 0; j < 4; j++)
            v[j] = *reinterpret_cast<const float4*>(ag + c * 32 + j * 4);
    };
    auto stsA = [&](int s, const float4* v) {
        const uint32_t sb = smb + s * STG + OA;
        sts16(sb + asts[0], packh2(v[0].x, v[0].y), packh2(v[0].z, v[0].w),
                            packh2(v[1].x, v[1].y), packh2(v[1].z, v[1].w));
        sts16(sb + asts[1], packh2(v[2].x, v[2].y), packh2(v[2].z, v[2].w),
                            packh2(v[3].x, v[3].y), packh2(v[3].z, v[3].w));
    };

    // ---- prologue: B chunks 0..2 in flight, A chunks 0,1 staged ----
    cpB(0, 0);
    cpB(1, 1);
    cpB(2, 2);
    {
        float4 a0[4];
        ldA(0, a0);
        stsA(0, a0);
        float4 a1[4];
        ldA(1, a1);
        stsA(1, a1);
    }
    asm volatile("cp.async.wait_group 2;" ::: "memory");
    __syncthreads();

    // ---- mainloop: one barrier per chunk ----
    for (int c = 0; c < NCHUNK; c++) {
        const int s = c & 3;
        const uint32_t sb = smb + s * STG;

        float4 av[4];
        if (c + 2 < NCHUNK) ldA(c + 2, av);        // LDG hidden under MMAs
        if (c + 3 < NCHUNK) cpB(c + 3, (c + 3) & 3);

        #pragma unroll
        for (int h = 0; h < 2; h++) {
            const uint32_t aswz = swz(aoff_lin + h * 32);
            const uint32_t bswz = swz(boff_lin + h * 32);
            uint32_t A[4][4], B[4][4];
            #pragma unroll
            for (int mi = 0; mi < 4; mi++) ldmx4(A[mi], sb + OA + aswz + mi * 1024);
            #pragma unroll
            for (int g = 0; g < 4; g++) ldmx4(B[g], sb + OB + bswz + g * 1024);

            #pragma unroll
            for (int g = 0; g < 4; g++)
                #pragma unroll
                for (int gg = 0; gg < 2; gg++) {
                    const int nf = 2 * g + gg;
                    #pragma unroll
                    for (int mi = 0; mi < 4; mi++)
                        mma16816(acc[mi][nf], A[mi], B[g][gg * 2], B[g][gg * 2 + 1]);
                }
        }

        if (c + 2 < NCHUNK) stsA((c + 2) & 3, av);
        if (c < NCHUNK - 1) {
            // ensure stage c+1's B is complete before next iteration
            if (c + 3 < NCHUNK) {
                asm volatile("cp.async.wait_group 2;" ::: "memory");
            } else if (c + 2 < NCHUNK) {
                asm volatile("cp.async.wait_group 1;" ::: "memory");
            } else {
                asm volatile("cp.async.wait_group 0;" ::: "memory");
            }
            __syncthreads();
        }
    }

    // ---- epilogue: registers -> gmem, scale 1/16 ----
    const float sc = 0.0625f;
    float* ob = out + (size_t)node * 256;
    const int ecol0 = wn * 64 + (lane & 3) * 2;
    #pragma unroll
    for (int mi = 0; mi < 4; mi++) {
        const int erow = m0 + wm * 64 + mi * 16 + (lane >> 2);
        #pragma unroll
        for (int nf = 0; nf < 8; nf++) {
            float* p0 = ob + (size_t)erow * RS + ecol0 + nf * 8;
            float* p1 = p0 + (size_t)8 * RS;
            float2 v0, v1;
            v0.x = acc[mi][nf][0] * sc; v0.y = acc[mi][nf][1] * sc;
            v1.x = acc[mi][nf][2] * sc; v1.y = acc[mi][nf][3] * sc;
            *reinterpret_cast<float2*>(p0) = v0;
            *reinterpret_cast<float2*>(p1) = v1;
        }
    }
}

// ======================= launch =======================
extern "C" void kernel_launch(void* const* d_in, const int* in_sizes, int n_in,
                              void* d_out, int out_size)
{
    const float* x = (const float*)d_in[0];   // [262144, 256] f32
    const float* W = (const float*)d_in[2];   // [64, 256, 256] f32
    float*     out = (float*)d_out;

    cudaFuncSetAttribute(node_gemm_hmma, cudaFuncAttributeMaxDynamicSharedMemorySize, SMEM_TOTAL);

    prep_w<<<NUM_NODES * 8, 256>>>(W);
    node_gemm_hmma<<<dim3(BATCH / BM, NUM_NODES), THREADS, SMEM_TOTAL>>>(x, out);
}